// round 11
// baseline (speedup 1.0000x reference)
#include <cuda_runtime.h>
#include <cstdint>

#define NN 2048
#define BB 4
#define THREADS 128
#define ROWS_PER_BLOCK 8                         // 2 row-groups x 4 rows
#define BLOCKS_PER_BATCH (NN / ROWS_PER_BLOCK)   // 256
#define NWIN 32                                  // 1024 j per warp / 32
#define NSTAGES 3
#define STAGE_BYTES 1024                         // [Wr0|Ar0|Wr1|Ar1|Wr2|Ar2|Wr3|Ar3] x128B

typedef unsigned long long u64;

__device__ __forceinline__ void fma2(u64& d, u64 a, u64 b) {
    asm("fma.rn.f32x2 %0, %1, %2, %0;" : "+l"(d) : "l"(a), "l"(b));
}
__device__ __forceinline__ u64 pack2(float lo, float hi) {
    u64 r;
    asm("mov.b64 %0, {%1, %2};" : "=l"(r) : "f"(lo), "f"(hi));
    return r;
}
__device__ __forceinline__ void unpack2(float& lo, float& hi, u64 v) {
    asm("mov.b64 {%0, %1}, %2;" : "=f"(lo), "=f"(hi) : "l"(v));
}
__device__ __forceinline__ u64 add2(u64 a, u64 b) {
    u64 r;
    asm("add.rn.f32x2 %0, %1, %2;" : "=l"(r) : "l"(a), "l"(b));
    return r;
}
__device__ __forceinline__ void cp16(uint32_t dst_smem, const void* src) {
    asm volatile("cp.async.cg.shared.global [%0], [%1], 16;"
                 :: "r"(dst_smem), "l"(src));
}
#define CP_COMMIT() asm volatile("cp.async.commit_group;")
#define CP_WAIT2()  asm volatile("cp.async.wait_group 2;")

__global__ __launch_bounds__(THREADS, 7)
void kuramoto_kernel(const float* __restrict__ W,
                     const float* __restrict__ alpha,
                     const float4* __restrict__ theta,
                     const float4* __restrict__ gamma,
                     float4* __restrict__ out) {
    __shared__ __align__(16) char stage[4][NSTAGES][STAGE_BYTES]; // 12 KB
    __shared__ u64 red[4][4][4];                                  // [warp][r][4]

    const int b    = blockIdx.x / BLOCKS_PER_BATCH;
    const int row0 = (blockIdx.x % BLOCKS_PER_BATCH) * ROWS_PER_BLOCK;
    const int base = b * NN;

    const int warp   = threadIdx.x >> 5;
    const int lane   = threadIdx.x & 31;
    const int rowgrp = warp >> 1;             // rows 0-3 / 4-7
    const int jpart  = warp & 1;              // j half: [0,1024) or [1024,2048)
    const int i0     = row0 + rowgrp * 4;     // first of this warp's 4 rows

    const float* __restrict__ Wr = W     + (size_t)(base + i0) * NN;
    const float* __restrict__ Ar = alpha + (size_t)(base + i0) * NN;

    // cp.async lane mapping: q = lane>>3 -> [W r0][A r0][W r1][A r1]; second
    // cp16 covers rows 2,3. src element offset within a row = 4*(lane&7).
    const int  q       = lane >> 3;
    const int  cp_row  = (q >> 1);                     // 0 or 1
    const bool cp_isA  = (q & 1);
    const float* __restrict__ cp_base = cp_isA ? Ar : Wr;
    const size_t cp_off1 = (size_t)cp_row * NN + 4 * (lane & 7);
    const size_t cp_off2 = cp_off1 + 2 * (size_t)NN;   // rows 2,3

    const uint32_t my_stage =
        (uint32_t)__cvta_generic_to_shared(&stage[warp][0][0]) + lane * 16;
    const char* stage_rd = &stage[warp][0][0];

    const int jbase = jpart * 1024;           // this warp's contiguous j domain

    u64 P01[4], P23[4], Q01[4], Q23[4];
    #pragma unroll
    for (int r = 0; r < 4; ++r) { P01[r] = 0; P23[r] = 0; Q01[r] = 0; Q23[r] = 0; }

    // Prologue: prefetch windows 0..2
    #pragma unroll
    for (int w = 0; w < NSTAGES; ++w) {
        const int j0 = jbase + w * 32;
        const uint32_t dst = my_stage + w * STAGE_BYTES;
        cp16(dst,       cp_base + cp_off1 + j0);
        cp16(dst + 512, cp_base + cp_off2 + j0);
        CP_COMMIT();
    }

    for (int w = 0; w < NWIN; ++w) {
        const int j0 = jbase + w * 32;

        // Theta sincos for this lane's j — issued BEFORE the pipeline wait so
        // the LDG (L2-hit) + MUFU latency overlaps the cp.async wait.
        const float4 th = theta[base + j0 + lane];
        float4 sj, cj;
        __sincosf(th.x, &sj.x, &cj.x);
        __sincosf(th.y, &sj.y, &cj.y);
        __sincosf(th.z, &sj.z, &cj.z);
        __sincosf(th.w, &sj.w, &cj.w);
        const u64 sjx = pack2(sj.x, sj.y), sjy = pack2(sj.z, sj.w);
        const u64 cjx = pack2(cj.x, cj.y), cjy = pack2(cj.z, cj.w);

        CP_WAIT2();            // window w's group complete (2 groups stay in flight)
        __syncwarp();          // cross-lane visibility of staged bytes

        const int slot = w % NSTAGES;
        const char* st = stage_rd + slot * STAGE_BYTES;

        #pragma unroll
        for (int r = 0; r < 4; ++r) {
            const float wv = *reinterpret_cast<const float*>(st + r * 256 + lane * 4);
            const float av = *reinterpret_cast<const float*>(st + r * 256 + 128 + lane * 4);
            float sa, ca;
            __sincosf(av, &sa, &ca);
            const float Av = wv * ca;            // W * cos(alpha)
            const float Bv = wv * sa;            // W * sin(alpha)
            const u64 Av2  = pack2(Av, Av);
            const u64 Bv2  = pack2(Bv, Bv);
            const u64 nBv2 = pack2(-Bv, -Bv);
            // P += Av*c + Bv*s ;  Q += Av*s - Bv*c   (packed d-pairs)
            fma2(P01[r], Av2, cjx);  fma2(P01[r], Bv2, sjx);
            fma2(P23[r], Av2, cjy);  fma2(P23[r], Bv2, sjy);
            fma2(Q01[r], Av2, sjx);  fma2(Q01[r], nBv2, cjx);
            fma2(Q23[r], Av2, sjy);  fma2(Q23[r], nBv2, cjy);
        }

        __syncwarp();          // all lanes done reading slot before overwrite
        if (w + NSTAGES < NWIN) {
            const int jn = jbase + (w + NSTAGES) * 32;
            const uint32_t dst = my_stage + slot * STAGE_BYTES;
            cp16(dst,       cp_base + cp_off1 + jn);
            cp16(dst + 512, cp_base + cp_off2 + jn);
        }
        CP_COMMIT();           // keep group accounting uniform
    }

    // Butterfly: reduce all 4 rows' packed sums across the 32 lanes
    #pragma unroll
    for (int off = 16; off > 0; off >>= 1) {
        #pragma unroll
        for (int r = 0; r < 4; ++r) {
            P01[r] = add2(P01[r], __shfl_xor_sync(0xffffffffu, P01[r], off));
            P23[r] = add2(P23[r], __shfl_xor_sync(0xffffffffu, P23[r], off));
            Q01[r] = add2(Q01[r], __shfl_xor_sync(0xffffffffu, Q01[r], off));
            Q23[r] = add2(Q23[r], __shfl_xor_sync(0xffffffffu, Q23[r], off));
        }
    }

    if (lane == 0) {
        #pragma unroll
        for (int r = 0; r < 4; ++r) {
            red[warp][r][0] = P01[r];  red[warp][r][1] = P23[r];
            red[warp][r][2] = Q01[r];  red[warp][r][3] = Q23[r];
        }
    }
    __syncthreads();

    // 8 threads: one output row each; combine the two j-half warps
    if (threadIdx.x < ROWS_PER_BLOCK) {
        const int g = threadIdx.x >> 2;      // row-group
        const int r = threadIdx.x & 3;       // row within group
        const int i = row0 + g * 4 + r;

        const u64 p01 = add2(red[2 * g][r][0], red[2 * g + 1][r][0]);
        const u64 p23 = add2(red[2 * g][r][1], red[2 * g + 1][r][1]);
        const u64 q01 = add2(red[2 * g][r][2], red[2 * g + 1][r][2]);
        const u64 q23 = add2(red[2 * g][r][3], red[2 * g + 1][r][3]);

        float P0, P1, P2, P3, Q0, Q1, Q2, Q3;
        unpack2(P0, P1, p01); unpack2(P2, P3, p23);
        unpack2(Q0, Q1, q01); unpack2(Q2, Q3, q23);

        const float invn = 1.0f / (float)NN;     // COUPLING / N
        const float4 g4 = gamma[base + i];
        const float4 th = theta[base + i];
        float4 si, ci;
        __sincosf(th.x, &si.x, &ci.x);
        __sincosf(th.y, &si.y, &ci.y);
        __sincosf(th.z, &si.z, &ci.z);
        __sincosf(th.w, &si.w, &ci.w);

        // theta_next = gamma + (1/N)(c_i*Q - s_i*P)   (theta cancels, DT=ATTR=1)
        float n0 = g4.x + invn * (ci.x * Q0 - si.x * P0);
        float n1 = g4.y + invn * (ci.y * Q1 - si.y * P1);
        float n2 = g4.z + invn * (ci.z * Q2 - si.z * P2);
        float n3 = g4.w + invn * (ci.w * Q3 - si.w * P3);

        float nrm = sqrtf(n0 * n0 + n1 * n1 + n2 * n2 + n3 * n3);
        float inv = 1.0f / fmaxf(nrm, 1e-6f);
        out[base + i] = make_float4(n0 * inv, n1 * inv, n2 * inv, n3 * inv);
    }
}

extern "C" void kernel_launch(void* const* d_in, const int* in_sizes, int n_in,
                              void* d_out, int out_size) {
    const float* theta = (const float*)d_in[0];   // [B, N, 4]
    const float* gamma = (const float*)d_in[1];   // [B, N, 4]
    const float* W     = (const float*)d_in[2];   // [B, N, N]
    const float* alpha = (const float*)d_in[3];   // [B, N, N]
    float* out = (float*)d_out;                   // [B, N, 4]

    // Table-free design: per-lane register sincos of theta (contiguous j per
    // warp), cp.async pipeline for W/alpha, zero block barriers in mainloop.
    kuramoto_kernel<<<BB * BLOCKS_PER_BATCH, THREADS>>>(
        W, alpha, (const float4*)theta, (const float4*)gamma, (float4*)out);
}